// round 12
// baseline (speedup 1.0000x reference)
#include <cuda_runtime.h>
#include <cuda_fp16.h>
#include <cstdint>

#define B_DIM 32
#define D_DIM 256
#define T_DIM 2048
#define K_CODES 1024
#define N_TOT (B_DIM * T_DIM)
#define Q_ELEMS (B_DIM * D_DIM * T_DIM)
#define LOSS_OFF Q_ELEMS
#define IDX_OFF (Q_ELEMS + 1)
#define KW 512                       // extended row: [hi(256)|lo(256)]

#define XBUF (128 * 72 * 2)
#define EBUF (128 * 72 * 2)
#define NSTAGE 3
#define OFF_ES (NSTAGE * XBUF)
#define OFF_EN (NSTAGE * (XBUF + EBUF))
#define SMEM_DYN (OFF_EN + 512)

__device__ float g_enorm[K_CODES];
__device__ unsigned long long g_best[N_TOT];
__device__ __half g_Xext[(size_t)N_TOT * KW];
__device__ __half g_Eext[(size_t)K_CODES * KW];

__device__ __forceinline__ uint32_t s2u(const void* p) {
    uint32_t a;
    asm("{ .reg .u64 t; cvta.to.shared.u64 t, %1; cvt.u32.u64 %0, t; }" : "=r"(a) : "l"(p));
    return a;
}
__device__ __forceinline__ void cp16(uint32_t d, const void* s) {
    asm volatile("cp.async.cg.shared.global [%0], [%1], 16;" :: "r"(d), "l"(s) : "memory");
}
__device__ __forceinline__ uint4 ldsm4(uint32_t a) {
    uint4 r;
    asm volatile("ldmatrix.sync.aligned.m8n8.x4.shared.b16 {%0,%1,%2,%3}, [%4];"
                 : "=r"(r.x), "=r"(r.y), "=r"(r.z), "=r"(r.w) : "r"(a));
    return r;
}
__device__ __forceinline__ void mma16816(float* d, uint4 a, uint32_t b0, uint32_t b1) {
    asm volatile("mma.sync.aligned.m16n8k16.row.col.f32.f16.f16.f32 "
                 "{%0,%1,%2,%3},{%4,%5,%6,%7},{%8,%9},{%0,%1,%2,%3};"
                 : "+f"(d[0]), "+f"(d[1]), "+f"(d[2]), "+f"(d[3])
                 : "r"(a.x), "r"(a.y), "r"(a.z), "r"(a.w), "r"(b0), "r"(b1));
}
__device__ __forceinline__ uint32_t mono(float f) {
    uint32_t u = __float_as_uint(f);
    return (u & 0x80000000u) ? ~u : (u | 0x80000000u);
}

// Merged prep: blocks [0,128) = E convert + norms + loss init;
// blocks [128,128+2048) = X transpose/split + g_best init.
__global__ void __launch_bounds__(256) prep_kernel(const float* __restrict__ X,
                                                   const float* __restrict__ E,
                                                   float* __restrict__ out) {
    if (blockIdx.x < 128) {
        if (blockIdx.x == 0 && threadIdx.x == 0) out[LOSS_OFF] = 0.0f;
        int k = blockIdx.x * 8 + (threadIdx.x >> 5);
        int lane = threadIdx.x & 31;
        const float* er = E + (size_t)k * D_DIM;
        __align__(16) __half hb[8], lb[8];
        float s = 0.f;
        #pragma unroll
        for (int q = 0; q < 8; q++) {
            float x = er[lane * 8 + q];
            s = fmaf(x, x, s);
            __half h = __float2half_rn(x);
            hb[q] = h;
            lb[q] = __float2half_rn(x - __half2float(h));
        }
        __half* row = g_Eext + (size_t)k * KW;
        *(uint4*)(row + lane * 8) = *(uint4*)hb;
        *(uint4*)(row + 256 + lane * 8) = *(uint4*)lb;
        #pragma unroll
        for (int o = 16; o; o >>= 1) s += __shfl_down_sync(0xffffffffu, s, o);
        if (lane == 0) g_enorm[k] = 0.5f * s;
        return;
    }
    int bx = blockIdx.x - 128;
    int by = bx >> 6, bt = bx & 63;
    if (threadIdx.x < 32) g_best[bx * 32 + threadIdx.x] = ~0ull;
    __shared__ float tile[256][33];
    int lane = threadIdx.x & 31, w = threadIdx.x >> 5;
    const float* src = X + (size_t)by * D_DIM * T_DIM + bt * 32;
    #pragma unroll 8
    for (int r = 0; r < 32; r++) {
        int d = w + r * 8;
        tile[d][lane] = src[(size_t)d * T_DIM + lane];
    }
    __syncthreads();
    for (int i = 0; i < 4; i++) {
        int nl = w * 4 + i;
        int n = by * T_DIM + bt * 32 + nl;
        __align__(16) __half hb[8], lb[8];
        #pragma unroll
        for (int q = 0; q < 8; q++) {
            float x = tile[lane * 8 + q][nl];
            __half h = __float2half_rn(x);
            hb[q] = h;
            lb[q] = __float2half_rn(x - __half2float(h));
        }
        __half* row = g_Xext + (size_t)n * KW;
        *(uint4*)(row + lane * 8) = *(uint4*)hb;
        *(uint4*)(row + 256 + lane * 8) = *(uint4*)lb;
    }
}

// Argmin GEMM: CTA = 128 threads (4 warps, 2m x 2n), tile 128 x-rows x
// 128 codes, warp tile 64x64. 12 chunks of K=64 (hi.hi, lo.hi, hi.lo),
// 3-stage cp.async (load after compute), 2 CTAs/SM.
__global__ void __launch_bounds__(128, 2) vqmma_kernel() {
    extern __shared__ char sm[];
    const uint32_t sb = s2u(sm);
    float* en_s = (float*)(sm + OFF_EN);
    const int tid = threadIdx.x, wid = tid >> 5, lane = tid & 31;
    const int k0 = blockIdx.x * 128, n0 = blockIdx.y * 128;
    const int mw = wid & 1, nw = wid >> 1;   // 2 m-warps x 2 n-warps

    en_s[tid] = g_enorm[k0 + tid];

    float acc[128];
    #pragma unroll
    for (int i = 0; i < 128; i++) acc[i] = 0.f;

    auto load = [&](int g) {
        int t = g >> 2, c = (g & 3) * 64, buf = g % 3;
        int xoff = (t == 1 ? 256 : 0) + c;   // hi, lo, hi
        int eoff = (t == 2 ? 256 : 0) + c;   // hi, hi, lo
        const __half* xs = g_Xext + (size_t)n0 * KW + xoff;
        const __half* es = g_Eext + (size_t)k0 * KW + eoff;
        uint32_t xb = sb + buf * XBUF;
        uint32_t eb = sb + OFF_ES + buf * EBUF;
        #pragma unroll
        for (int q = 0; q < 8; q++) {
            int id = tid + q * 128, r = id >> 3, cc = id & 7;
            cp16(xb + (r * 72 + cc * 8) * 2, xs + (size_t)r * KW + cc * 8);
            cp16(eb + (r * 72 + cc * 8) * 2, es + (size_t)r * KW + cc * 8);
        }
        asm volatile("cp.async.commit_group;" ::: "memory");
    };

    load(0); load(1);

    const int l7 = lane & 7;
    const int arow = ((lane >> 3) & 1) * 8, akc = (lane >> 4) * 8;
    const int brow = (lane >> 4) * 8, bkc = ((lane >> 3) & 1) * 8;

    for (int g = 0; g < 12; g++) {
        if (g < 11) asm volatile("cp.async.wait_group 1;" ::: "memory");
        else        asm volatile("cp.async.wait_group 0;" ::: "memory");
        __syncthreads();
        int buf = g % 3;
        uint32_t xb = sb + buf * XBUF;
        uint32_t eb = sb + OFF_ES + buf * EBUF;
        #pragma unroll
        for (int ks = 0; ks < 4; ks++) {
            int kk = ks * 16;
            uint4 B[4];
            #pragma unroll
            for (int p = 0; p < 4; p++) {
                int nb = nw * 64 + p * 16;
                B[p] = ldsm4(eb + ((nb + l7 + brow) * 72 + kk + bkc) * 2);
            }
            #pragma unroll
            for (int mt = 0; mt < 4; mt++) {
                int m0 = mw * 64 + mt * 16;
                uint4 A = ldsm4(xb + ((m0 + l7 + arow) * 72 + kk + akc) * 2);
                #pragma unroll
                for (int p = 0; p < 4; p++) {
                    mma16816(&acc[(mt * 8 + p * 2 + 0) * 4], A, B[p].x, B[p].y);
                    mma16816(&acc[(mt * 8 + p * 2 + 1) * 4], A, B[p].z, B[p].w);
                }
            }
        }
        if (g + 2 < 12) load(g + 2);   // buf (g-1)%3, consumed last iter
    }

    // Argmin epilogue -> atomicMin packed (monotone score, code):
    // exact jnp.argmin first-index tie-break.
    #pragma unroll
    for (int mt = 0; mt < 4; mt++) {
        #pragma unroll
        for (int h = 0; h < 2; h++) {
            unsigned long long best = ~0ull;
            #pragma unroll
            for (int p = 0; p < 4; p++)
                #pragma unroll
                for (int b8 = 0; b8 < 2; b8++)
                    #pragma unroll
                    for (int c2 = 0; c2 < 2; c2++) {
                        int cl = nw * 64 + p * 16 + b8 * 8 + (lane & 3) * 2 + c2;
                        float sc = en_s[cl] - acc[(mt * 8 + p * 2 + b8) * 4 + h * 2 + c2];
                        unsigned long long pk =
                            ((unsigned long long)mono(sc) << 32) | (unsigned)(k0 + cl);
                        if (pk < best) best = pk;
                    }
            unsigned long long o1 = __shfl_xor_sync(0xffffffffu, best, 1);
            if (o1 < best) best = o1;
            unsigned long long o2 = __shfl_xor_sync(0xffffffffu, best, 2);
            if (o2 < best) best = o2;
            if ((lane & 3) == 0) {
                int row = n0 + mw * 64 + mt * 16 + (lane >> 2) + h * 8;
                atomicMin(&g_best[row], best);
            }
        }
    }
}

// Gather + transpose-write + loss; parallel over 4 D-segments per row.
__global__ void __launch_bounds__(256) gather_loss_kernel(const float* __restrict__ X,
                                                          const float* __restrict__ E,
                                                          float* __restrict__ out) {
    __shared__ float ws[8];
    int t = blockIdx.x * 64 + (threadIdx.x & 63);
    int dseg = threadIdx.x >> 6;
    int b = blockIdx.y;
    int n = b * T_DIM + t;
    int j = (int)(unsigned)(g_best[n] & 0xffffffffull);
    if (dseg == 0) out[IDX_OFF + n] = (float)j;
    const float* er = E + (size_t)j * D_DIM + dseg * 64;
    const float* xr = X + (size_t)b * D_DIM * T_DIM + (size_t)dseg * 64 * T_DIM + t;
    float* orow = out + (size_t)b * D_DIM * T_DIM + (size_t)dseg * 64 * T_DIM + t;
    float s = 0.f;
    #pragma unroll 4
    for (int d = 0; d < 64; d += 4) {
        float4 e4 = *(const float4*)(er + d);
        float x0 = xr[(size_t)(d + 0) * T_DIM], x1 = xr[(size_t)(d + 1) * T_DIM];
        float x2 = xr[(size_t)(d + 2) * T_DIM], x3 = xr[(size_t)(d + 3) * T_DIM];
        orow[(size_t)(d + 0) * T_DIM] = e4.x;
        orow[(size_t)(d + 1) * T_DIM] = e4.y;
        orow[(size_t)(d + 2) * T_DIM] = e4.z;
        orow[(size_t)(d + 3) * T_DIM] = e4.w;
        float d0 = e4.x - x0, d1 = e4.y - x1, d2 = e4.z - x2, d3 = e4.w - x3;
        s = fmaf(d0, d0, s); s = fmaf(d1, d1, s); s = fmaf(d2, d2, s); s = fmaf(d3, d3, s);
    }
    #pragma unroll
    for (int o = 16; o; o >>= 1) s += __shfl_down_sync(0xffffffffu, s, o);
    if ((threadIdx.x & 31) == 0) ws[threadIdx.x >> 5] = s;
    __syncthreads();
    if (threadIdx.x < 8) {
        float v = ws[threadIdx.x];
        #pragma unroll
        for (int o = 4; o; o >>= 1) v += __shfl_down_sync(0xffu, v, o);
        if (threadIdx.x == 0) atomicAdd(out + LOSS_OFF, v * (0.5f / (float)Q_ELEMS));
    }
}

extern "C" void kernel_launch(void* const* d_in, const int* in_sizes, int n_in,
                              void* d_out, int out_size) {
    const float* X = (const float*)d_in[0];
    const float* E = (const float*)d_in[1];
    float* out = (float*)d_out;
    prep_kernel<<<128 + 2048, 256>>>(X, E, out);
    cudaFuncSetAttribute(vqmma_kernel, cudaFuncAttributeMaxDynamicSharedMemorySize, SMEM_DYN);
    // ktile-major grid: 8 CTAs sharing an x-tile are bid-adjacent -> L2 reuse of X.
    vqmma_kernel<<<dim3(K_CODES / 128, N_TOT / 128), 128, SMEM_DYN>>>();
    gather_loss_kernel<<<dim3(T_DIM / 64, B_DIM), 256>>>(X, E, out);
}

// round 13
// speedup vs baseline: 1.0265x; 1.0265x over previous
#include <cuda_runtime.h>
#include <cuda_fp16.h>
#include <cstdint>

#define B_DIM 32
#define D_DIM 256
#define T_DIM 2048
#define K_CODES 1024
#define N_TOT (B_DIM * T_DIM)
#define Q_ELEMS (B_DIM * D_DIM * T_DIM)
#define LOSS_OFF Q_ELEMS
#define IDX_OFF (Q_ELEMS + 1)
#define KW 512                       // extended row: [hi(256)|lo(256)]

#define XBUF (128 * 72 * 2)
#define EBUF (128 * 72 * 2)
#define NSTAGE 3
#define OFF_ES (NSTAGE * XBUF)
#define OFF_EN (NSTAGE * (XBUF + EBUF))
#define SMEM_DYN (OFF_EN + 512)

__device__ float g_enorm[K_CODES];
__device__ unsigned long long g_best[N_TOT];
__device__ __half g_Xext[(size_t)N_TOT * KW];
__device__ __half g_Eext[(size_t)K_CODES * KW];

__device__ __forceinline__ uint32_t s2u(const void* p) {
    uint32_t a;
    asm("{ .reg .u64 t; cvta.to.shared.u64 t, %1; cvt.u32.u64 %0, t; }" : "=r"(a) : "l"(p));
    return a;
}
__device__ __forceinline__ void cp16(uint32_t d, const void* s) {
    asm volatile("cp.async.cg.shared.global [%0], [%1], 16;" :: "r"(d), "l"(s) : "memory");
}
__device__ __forceinline__ uint4 ldsm4(uint32_t a) {
    uint4 r;
    asm volatile("ldmatrix.sync.aligned.m8n8.x4.shared.b16 {%0,%1,%2,%3}, [%4];"
                 : "=r"(r.x), "=r"(r.y), "=r"(r.z), "=r"(r.w) : "r"(a));
    return r;
}
__device__ __forceinline__ void mma16816(float* d, uint4 a, uint32_t b0, uint32_t b1) {
    asm volatile("mma.sync.aligned.m16n8k16.row.col.f32.f16.f16.f32 "
                 "{%0,%1,%2,%3},{%4,%5,%6,%7},{%8,%9},{%0,%1,%2,%3};"
                 : "+f"(d[0]), "+f"(d[1]), "+f"(d[2]), "+f"(d[3])
                 : "r"(a.x), "r"(a.y), "r"(a.z), "r"(a.w), "r"(b0), "r"(b1));
}
__device__ __forceinline__ uint32_t mono(float f) {
    uint32_t u = __float_as_uint(f);
    return (u & 0x80000000u) ? ~u : (u | 0x80000000u);
}

// Merged prep: blocks [0,128) = E convert + norms + loss init;
// blocks [128,128+2048) = X transpose/split + g_best init.
__global__ void __launch_bounds__(256) prep_kernel(const float* __restrict__ X,
                                                   const float* __restrict__ E,
                                                   float* __restrict__ out) {
    if (blockIdx.x < 128) {
        if (blockIdx.x == 0 && threadIdx.x == 0) out[LOSS_OFF] = 0.0f;
        int k = blockIdx.x * 8 + (threadIdx.x >> 5);
        int lane = threadIdx.x & 31;
        const float* er = E + (size_t)k * D_DIM;
        __align__(16) __half hb[8], lb[8];
        float s = 0.f;
        #pragma unroll
        for (int q = 0; q < 8; q++) {
            float x = er[lane * 8 + q];
            s = fmaf(x, x, s);
            __half h = __float2half_rn(x);
            hb[q] = h;
            lb[q] = __float2half_rn(x - __half2float(h));
        }
        __half* row = g_Eext + (size_t)k * KW;
        *(uint4*)(row + lane * 8) = *(uint4*)hb;
        *(uint4*)(row + 256 + lane * 8) = *(uint4*)lb;
        #pragma unroll
        for (int o = 16; o; o >>= 1) s += __shfl_down_sync(0xffffffffu, s, o);
        if (lane == 0) g_enorm[k] = 0.5f * s;
        return;
    }
    int bx = blockIdx.x - 128;
    int by = bx >> 6, bt = bx & 63;
    if (threadIdx.x < 32) g_best[bx * 32 + threadIdx.x] = ~0ull;
    __shared__ float tile[256][33];
    int lane = threadIdx.x & 31, w = threadIdx.x >> 5;
    const float* src = X + (size_t)by * D_DIM * T_DIM + bt * 32;
    #pragma unroll 8
    for (int r = 0; r < 32; r++) {
        int d = w + r * 8;
        tile[d][lane] = src[(size_t)d * T_DIM + lane];
    }
    __syncthreads();
    for (int i = 0; i < 4; i++) {
        int nl = w * 4 + i;
        int n = by * T_DIM + bt * 32 + nl;
        __align__(16) __half hb[8], lb[8];
        #pragma unroll
        for (int q = 0; q < 8; q++) {
            float x = tile[lane * 8 + q][nl];
            __half h = __float2half_rn(x);
            hb[q] = h;
            lb[q] = __float2half_rn(x - __half2float(h));
        }
        __half* row = g_Xext + (size_t)n * KW;
        *(uint4*)(row + lane * 8) = *(uint4*)hb;
        *(uint4*)(row + 256 + lane * 8) = *(uint4*)lb;
    }
}

// Argmin GEMM (R7/R11 schedule, verbatim): CTA = 128 x-rows x 128 codes,
// 12 chunks of K=64 (hi.hi, lo.hi, hi.lo), 3-stage cp.async (load after
// compute), 2 CTAs/SM, 8 warps of 64x32.
__global__ void __launch_bounds__(256, 2) vqmma_kernel() {
    extern __shared__ char sm[];
    const uint32_t sb = s2u(sm);
    float* en_s = (float*)(sm + OFF_EN);
    const int tid = threadIdx.x, wid = tid >> 5, lane = tid & 31;
    const int k0 = blockIdx.x * 128, n0 = blockIdx.y * 128;
    const int mw = wid & 1, nw = wid >> 1;   // 2 m-warps x 4 n-warps

    if (tid < 128) en_s[tid] = g_enorm[k0 + tid];

    float acc[64];
    #pragma unroll
    for (int i = 0; i < 64; i++) acc[i] = 0.f;

    auto load = [&](int g) {
        int t = g >> 2, c = (g & 3) * 64, buf = g % 3;
        int xoff = (t == 1 ? 256 : 0) + c;   // hi, lo, hi
        int eoff = (t == 2 ? 256 : 0) + c;   // hi, hi, lo
        const __half* xs = g_Xext + (size_t)n0 * KW + xoff;
        const __half* es = g_Eext + (size_t)k0 * KW + eoff;
        uint32_t xb = sb + buf * XBUF;
        uint32_t eb = sb + OFF_ES + buf * EBUF;
        #pragma unroll
        for (int q = 0; q < 4; q++) {
            int id = tid + q * 256, r = id >> 3, cc = id & 7;
            cp16(xb + (r * 72 + cc * 8) * 2, xs + (size_t)r * KW + cc * 8);
            cp16(eb + (r * 72 + cc * 8) * 2, es + (size_t)r * KW + cc * 8);
        }
        asm volatile("cp.async.commit_group;" ::: "memory");
    };

    load(0); load(1);

    const int l7 = lane & 7;
    const int arow = ((lane >> 3) & 1) * 8, akc = (lane >> 4) * 8;
    const int brow = (lane >> 4) * 8, bkc = ((lane >> 3) & 1) * 8;

    for (int g = 0; g < 12; g++) {
        if (g < 11) asm volatile("cp.async.wait_group 1;" ::: "memory");
        else        asm volatile("cp.async.wait_group 0;" ::: "memory");
        __syncthreads();
        int buf = g % 3;
        uint32_t xb = sb + buf * XBUF;
        uint32_t eb = sb + OFF_ES + buf * EBUF;
        #pragma unroll
        for (int ks = 0; ks < 4; ks++) {
            int kk = ks * 16;
            uint4 B[2];
            #pragma unroll
            for (int p = 0; p < 2; p++) {
                int nb = nw * 32 + p * 16;
                B[p] = ldsm4(eb + ((nb + l7 + brow) * 72 + kk + bkc) * 2);
            }
            #pragma unroll
            for (int mt = 0; mt < 4; mt++) {
                int m0 = mw * 64 + mt * 16;
                uint4 A = ldsm4(xb + ((m0 + l7 + arow) * 72 + kk + akc) * 2);
                #pragma unroll
                for (int p = 0; p < 2; p++) {
                    mma16816(&acc[(mt * 4 + p * 2 + 0) * 4], A, B[p].x, B[p].y);
                    mma16816(&acc[(mt * 4 + p * 2 + 1) * 4], A, B[p].z, B[p].w);
                }
            }
        }
        if (g + 2 < 12) load(g + 2);   // buf (g-1)%3, consumed last iter
    }

    // Argmin epilogue -> atomicMin packed (monotone score, code):
    // exact jnp.argmin first-index tie-break.
    #pragma unroll
    for (int mt = 0; mt < 4; mt++) {
        #pragma unroll
        for (int h = 0; h < 2; h++) {
            unsigned long long best = ~0ull;
            #pragma unroll
            for (int p = 0; p < 2; p++)
                #pragma unroll
                for (int b8 = 0; b8 < 2; b8++)
                    #pragma unroll
                    for (int c2 = 0; c2 < 2; c2++) {
                        int cl = nw * 32 + p * 16 + b8 * 8 + (lane & 3) * 2 + c2;
                        float sc = en_s[cl] - acc[(mt * 4 + p * 2 + b8) * 4 + h * 2 + c2];
                        unsigned long long pk =
                            ((unsigned long long)mono(sc) << 32) | (unsigned)(k0 + cl);
                        if (pk < best) best = pk;
                    }
            unsigned long long o1 = __shfl_xor_sync(0xffffffffu, best, 1);
            if (o1 < best) best = o1;
            unsigned long long o2 = __shfl_xor_sync(0xffffffffu, best, 2);
            if (o2 < best) best = o2;
            if ((lane & 3) == 0) {
                int row = n0 + mw * 64 + mt * 16 + (lane >> 2) + h * 8;
                atomicMin(&g_best[row], best);
            }
        }
    }
}

// Gather + transpose-write + loss. Each thread: one t, one 64-d segment,
// processed as two 32-d batches with explicit register arrays for MLP.
__global__ void __launch_bounds__(256) gather_loss_kernel(const float* __restrict__ X,
                                                          const float* __restrict__ E,
                                                          float* __restrict__ out) {
    __shared__ float ws[8];
    int t = blockIdx.x * 64 + (threadIdx.x & 63);
    int dseg = threadIdx.x >> 6;
    int b = blockIdx.y;
    int n = b * T_DIM + t;
    int j = (int)(unsigned)(g_best[n] & 0xffffffffull);
    if (dseg == 0) out[IDX_OFF + n] = (float)j;
    const float* er = E + (size_t)j * D_DIM + dseg * 64;
    const float* xr = X + (size_t)b * D_DIM * T_DIM + (size_t)dseg * 64 * T_DIM + t;
    float* orow = out + (size_t)b * D_DIM * T_DIM + (size_t)dseg * 64 * T_DIM + t;
    float s = 0.f;
    #pragma unroll
    for (int hh = 0; hh < 2; hh++) {
        const float* erh = er + hh * 32;
        const float* xrh = xr + (size_t)hh * 32 * T_DIM;
        float* orh = orow + (size_t)hh * 32 * T_DIM;
        float4 e4[8];
        float xv[32];
        #pragma unroll
        for (int i = 0; i < 8; i++) e4[i] = *(const float4*)(erh + i * 4);
        #pragma unroll
        for (int d = 0; d < 32; d++) xv[d] = xrh[(size_t)d * T_DIM];
        float ev[32];
        #pragma unroll
        for (int i = 0; i < 8; i++) {
            ev[i * 4 + 0] = e4[i].x; ev[i * 4 + 1] = e4[i].y;
            ev[i * 4 + 2] = e4[i].z; ev[i * 4 + 3] = e4[i].w;
        }
        #pragma unroll
        for (int d = 0; d < 32; d++) {
            orh[(size_t)d * T_DIM] = ev[d];
            float dd = ev[d] - xv[d];
            s = fmaf(dd, dd, s);
        }
    }
    #pragma unroll
    for (int o = 16; o; o >>= 1) s += __shfl_down_sync(0xffffffffu, s, o);
    if ((threadIdx.x & 31) == 0) ws[threadIdx.x >> 5] = s;
    __syncthreads();
    if (threadIdx.x < 8) {
        float v = ws[threadIdx.x];
        #pragma unroll
        for (int o = 4; o; o >>= 1) v += __shfl_down_sync(0xffu, v, o);
        if (threadIdx.x == 0) atomicAdd(out + LOSS_OFF, v * (0.5f / (float)Q_ELEMS));
    }
}

extern "C" void kernel_launch(void* const* d_in, const int* in_sizes, int n_in,
                              void* d_out, int out_size) {
    const float* X = (const float*)d_in[0];
    const float* E = (const float*)d_in[1];
    float* out = (float*)d_out;
    prep_kernel<<<128 + 2048, 256>>>(X, E, out);
    cudaFuncSetAttribute(vqmma_kernel, cudaFuncAttributeMaxDynamicSharedMemorySize, SMEM_DYN);
    // ktile-major grid: 8 CTAs sharing an x-tile are bid-adjacent -> L2 reuse of X.
    vqmma_kernel<<<dim3(K_CODES / 128, N_TOT / 128), 256, SMEM_DYN>>>();
    gather_loss_kernel<<<dim3(T_DIM / 64, B_DIM), 256>>>(X, E, out);
}

// round 14
// speedup vs baseline: 1.0403x; 1.0134x over previous
#include <cuda_runtime.h>
#include <cuda_fp16.h>
#include <cstdint>

#define B_DIM 32
#define D_DIM 256
#define T_DIM 2048
#define K_CODES 1024
#define N_TOT (B_DIM * T_DIM)
#define Q_ELEMS (B_DIM * D_DIM * T_DIM)
#define LOSS_OFF Q_ELEMS
#define IDX_OFF (Q_ELEMS + 1)
#define KW 512                       // extended row: [hi(256)|lo(256)]

#define XBUF (128 * 72 * 2)
#define EBUF (128 * 72 * 2)
#define NSTAGE 3
#define OFF_ES (NSTAGE * XBUF)
#define OFF_EN (NSTAGE * (XBUF + EBUF))
#define SMEM_DYN (OFF_EN + 512)

__device__ float g_enorm[K_CODES];
__device__ float g_xnorm[N_TOT];
__device__ unsigned long long g_best[N_TOT];
__device__ __half g_Xext[(size_t)N_TOT * KW];
__device__ __half g_Eext[(size_t)K_CODES * KW];

__device__ __forceinline__ uint32_t s2u(const void* p) {
    uint32_t a;
    asm("{ .reg .u64 t; cvta.to.shared.u64 t, %1; cvt.u32.u64 %0, t; }" : "=r"(a) : "l"(p));
    return a;
}
__device__ __forceinline__ void cp16(uint32_t d, const void* s) {
    asm volatile("cp.async.cg.shared.global [%0], [%1], 16;" :: "r"(d), "l"(s) : "memory");
}
__device__ __forceinline__ uint4 ldsm4(uint32_t a) {
    uint4 r;
    asm volatile("ldmatrix.sync.aligned.m8n8.x4.shared.b16 {%0,%1,%2,%3}, [%4];"
                 : "=r"(r.x), "=r"(r.y), "=r"(r.z), "=r"(r.w) : "r"(a));
    return r;
}
__device__ __forceinline__ void mma16816(float* d, uint4 a, uint32_t b0, uint32_t b1) {
    asm volatile("mma.sync.aligned.m16n8k16.row.col.f32.f16.f16.f32 "
                 "{%0,%1,%2,%3},{%4,%5,%6,%7},{%8,%9},{%0,%1,%2,%3};"
                 : "+f"(d[0]), "+f"(d[1]), "+f"(d[2]), "+f"(d[3])
                 : "r"(a.x), "r"(a.y), "r"(a.z), "r"(a.w), "r"(b0), "r"(b1));
}
__device__ __forceinline__ uint32_t mono(float f) {
    uint32_t u = __float_as_uint(f);
    return (u & 0x80000000u) ? ~u : (u | 0x80000000u);
}
__device__ __forceinline__ float unmono(uint32_t v) {
    uint32_t u = (v & 0x80000000u) ? (v & 0x7fffffffu) : ~v;
    return __uint_as_float(u);
}

// Merged prep: blocks [0,128) = E convert + norms + loss init;
// blocks [128,128+2048) = X transpose/split + ||x_n||^2 + g_best init.
__global__ void __launch_bounds__(256) prep_kernel(const float* __restrict__ X,
                                                   const float* __restrict__ E,
                                                   float* __restrict__ out) {
    if (blockIdx.x < 128) {
        if (blockIdx.x == 0 && threadIdx.x == 0) out[LOSS_OFF] = 0.0f;
        int k = blockIdx.x * 8 + (threadIdx.x >> 5);
        int lane = threadIdx.x & 31;
        const float* er = E + (size_t)k * D_DIM;
        __align__(16) __half hb[8], lb[8];
        float s = 0.f;
        #pragma unroll
        for (int q = 0; q < 8; q++) {
            float x = er[lane * 8 + q];
            s = fmaf(x, x, s);
            __half h = __float2half_rn(x);
            hb[q] = h;
            lb[q] = __float2half_rn(x - __half2float(h));
        }
        __half* row = g_Eext + (size_t)k * KW;
        *(uint4*)(row + lane * 8) = *(uint4*)hb;
        *(uint4*)(row + 256 + lane * 8) = *(uint4*)lb;
        #pragma unroll
        for (int o = 16; o; o >>= 1) s += __shfl_down_sync(0xffffffffu, s, o);
        if (lane == 0) g_enorm[k] = 0.5f * s;
        return;
    }
    int bx = blockIdx.x - 128;
    int by = bx >> 6, bt = bx & 63;
    if (threadIdx.x < 32) g_best[bx * 32 + threadIdx.x] = ~0ull;
    __shared__ float tile[256][33];
    int lane = threadIdx.x & 31, w = threadIdx.x >> 5;
    const float* src = X + (size_t)by * D_DIM * T_DIM + bt * 32;
    #pragma unroll 8
    for (int r = 0; r < 32; r++) {
        int d = w + r * 8;
        tile[d][lane] = src[(size_t)d * T_DIM + lane];
    }
    __syncthreads();
    for (int i = 0; i < 4; i++) {
        int nl = w * 4 + i;
        int n = by * T_DIM + bt * 32 + nl;
        __align__(16) __half hb[8], lb[8];
        float s = 0.f;
        #pragma unroll
        for (int q = 0; q < 8; q++) {
            float x = tile[lane * 8 + q][nl];
            s = fmaf(x, x, s);
            __half h = __float2half_rn(x);
            hb[q] = h;
            lb[q] = __float2half_rn(x - __half2float(h));
        }
        __half* row = g_Xext + (size_t)n * KW;
        *(uint4*)(row + lane * 8) = *(uint4*)hb;
        *(uint4*)(row + 256 + lane * 8) = *(uint4*)lb;
        #pragma unroll
        for (int o = 16; o; o >>= 1) s += __shfl_down_sync(0xffffffffu, s, o);
        if (lane == 0) g_xnorm[n] = s;
    }
}

// Argmin GEMM (R7/R11 schedule, verbatim): CTA = 128 x-rows x 128 codes,
// 12 chunks of K=64 (hi.hi, lo.hi, hi.lo), 3-stage cp.async (load after
// compute), 2 CTAs/SM, 8 warps of 64x32.
__global__ void __launch_bounds__(256, 2) vqmma_kernel() {
    extern __shared__ char sm[];
    const uint32_t sb = s2u(sm);
    float* en_s = (float*)(sm + OFF_EN);
    const int tid = threadIdx.x, wid = tid >> 5, lane = tid & 31;
    const int k0 = blockIdx.x * 128, n0 = blockIdx.y * 128;
    const int mw = wid & 1, nw = wid >> 1;   // 2 m-warps x 4 n-warps

    if (tid < 128) en_s[tid] = g_enorm[k0 + tid];

    float acc[64];
    #pragma unroll
    for (int i = 0; i < 64; i++) acc[i] = 0.f;

    auto load = [&](int g) {
        int t = g >> 2, c = (g & 3) * 64, buf = g % 3;
        int xoff = (t == 1 ? 256 : 0) + c;   // hi, lo, hi
        int eoff = (t == 2 ? 256 : 0) + c;   // hi, hi, lo
        const __half* xs = g_Xext + (size_t)n0 * KW + xoff;
        const __half* es = g_Eext + (size_t)k0 * KW + eoff;
        uint32_t xb = sb + buf * XBUF;
        uint32_t eb = sb + OFF_ES + buf * EBUF;
        #pragma unroll
        for (int q = 0; q < 4; q++) {
            int id = tid + q * 256, r = id >> 3, cc = id & 7;
            cp16(xb + (r * 72 + cc * 8) * 2, xs + (size_t)r * KW + cc * 8);
            cp16(eb + (r * 72 + cc * 8) * 2, es + (size_t)r * KW + cc * 8);
        }
        asm volatile("cp.async.commit_group;" ::: "memory");
    };

    load(0); load(1);

    const int l7 = lane & 7;
    const int arow = ((lane >> 3) & 1) * 8, akc = (lane >> 4) * 8;
    const int brow = (lane >> 4) * 8, bkc = ((lane >> 3) & 1) * 8;

    for (int g = 0; g < 12; g++) {
        if (g < 11) asm volatile("cp.async.wait_group 1;" ::: "memory");
        else        asm volatile("cp.async.wait_group 0;" ::: "memory");
        __syncthreads();
        int buf = g % 3;
        uint32_t xb = sb + buf * XBUF;
        uint32_t eb = sb + OFF_ES + buf * EBUF;
        #pragma unroll
        for (int ks = 0; ks < 4; ks++) {
            int kk = ks * 16;
            uint4 B[2];
            #pragma unroll
            for (int p = 0; p < 2; p++) {
                int nb = nw * 32 + p * 16;
                B[p] = ldsm4(eb + ((nb + l7 + brow) * 72 + kk + bkc) * 2);
            }
            #pragma unroll
            for (int mt = 0; mt < 4; mt++) {
                int m0 = mw * 64 + mt * 16;
                uint4 A = ldsm4(xb + ((m0 + l7 + arow) * 72 + kk + akc) * 2);
                #pragma unroll
                for (int p = 0; p < 2; p++) {
                    mma16816(&acc[(mt * 4 + p * 2 + 0) * 4], A, B[p].x, B[p].y);
                    mma16816(&acc[(mt * 4 + p * 2 + 1) * 4], A, B[p].z, B[p].w);
                }
            }
        }
        if (g + 2 < 12) load(g + 2);   // buf (g-1)%3, consumed last iter
    }

    // Argmin epilogue -> atomicMin packed (monotone score, code):
    // exact jnp.argmin first-index tie-break.
    #pragma unroll
    for (int mt = 0; mt < 4; mt++) {
        #pragma unroll
        for (int h = 0; h < 2; h++) {
            unsigned long long best = ~0ull;
            #pragma unroll
            for (int p = 0; p < 2; p++)
                #pragma unroll
                for (int b8 = 0; b8 < 2; b8++)
                    #pragma unroll
                    for (int c2 = 0; c2 < 2; c2++) {
                        int cl = nw * 32 + p * 16 + b8 * 8 + (lane & 3) * 2 + c2;
                        float sc = en_s[cl] - acc[(mt * 4 + p * 2 + b8) * 4 + h * 2 + c2];
                        unsigned long long pk =
                            ((unsigned long long)mono(sc) << 32) | (unsigned)(k0 + cl);
                        if (pk < best) best = pk;
                    }
            unsigned long long o1 = __shfl_xor_sync(0xffffffffu, best, 1);
            if (o1 < best) best = o1;
            unsigned long long o2 = __shfl_xor_sync(0xffffffffu, best, 2);
            if (o2 < best) best = o2;
            if ((lane & 3) == 0) {
                int row = n0 + mw * 64 + mt * 16 + (lane >> 2) + h * 8;
                atomicMin(&g_best[row], best);
            }
        }
    }
}

// Gather + transpose-write + loss. No X reads: loss comes from the packed
// best score: ||x - e_j||^2 = ||x||^2 + 2*(0.5||e_j||^2 - x.e_j).
__global__ void __launch_bounds__(256) gather_loss_kernel(const float* __restrict__ E,
                                                          float* __restrict__ out) {
    __shared__ float ws[8];
    int t = blockIdx.x * 64 + (threadIdx.x & 63);
    int dseg = threadIdx.x >> 6;
    int b = blockIdx.y;
    int n = b * T_DIM + t;
    unsigned long long pk = g_best[n];
    int j = (int)(unsigned)(pk & 0xffffffffull);
    float s = 0.f;
    if (dseg == 0) {
        out[IDX_OFF + n] = (float)j;
        float score = unmono((uint32_t)(pk >> 32));
        s = g_xnorm[n] + 2.0f * score;        // ||x_n - e_j||^2
    }
    const float* er = E + (size_t)j * D_DIM + dseg * 64;
    float* orow = out + (size_t)b * D_DIM * T_DIM + (size_t)dseg * 64 * T_DIM + t;
    #pragma unroll 4
    for (int d = 0; d < 64; d += 4) {
        float4 e4 = *(const float4*)(er + d);
        orow[(size_t)(d + 0) * T_DIM] = e4.x;
        orow[(size_t)(d + 1) * T_DIM] = e4.y;
        orow[(size_t)(d + 2) * T_DIM] = e4.z;
        orow[(size_t)(d + 3) * T_DIM] = e4.w;
    }
    #pragma unroll
    for (int o = 16; o; o >>= 1) s += __shfl_down_sync(0xffffffffu, s, o);
    if ((threadIdx.x & 31) == 0) ws[threadIdx.x >> 5] = s;
    __syncthreads();
    if (threadIdx.x < 8) {
        float v = ws[threadIdx.x];
        #pragma unroll
        for (int o = 4; o; o >>= 1) v += __shfl_down_sync(0xffu, v, o);
        if (threadIdx.x == 0) atomicAdd(out + LOSS_OFF, v * (0.5f / (float)Q_ELEMS));
    }
}

extern "C" void kernel_launch(void* const* d_in, const int* in_sizes, int n_in,
                              void* d_out, int out_size) {
    const float* X = (const float*)d_in[0];
    const float* E = (const float*)d_in[1];
    float* out = (float*)d_out;
    prep_kernel<<<128 + 2048, 256>>>(X, E, out);
    cudaFuncSetAttribute(vqmma_kernel, cudaFuncAttributeMaxDynamicSharedMemorySize, SMEM_DYN);
    // ktile-major grid: 8 CTAs sharing an x-tile are bid-adjacent -> L2 reuse of X.
    vqmma_kernel<<<dim3(K_CODES / 128, N_TOT / 128), 256, SMEM_DYN>>>();
    gather_loss_kernel<<<dim3(T_DIM / 64, B_DIM), 256>>>(E, out);
}

// round 15
// speedup vs baseline: 1.0533x; 1.0125x over previous
#include <cuda_runtime.h>
#include <cuda_fp16.h>
#include <cstdint>

#define B_DIM 32
#define D_DIM 256
#define T_DIM 2048
#define K_CODES 1024
#define N_TOT (B_DIM * T_DIM)
#define Q_ELEMS (B_DIM * D_DIM * T_DIM)
#define LOSS_OFF Q_ELEMS
#define IDX_OFF (Q_ELEMS + 1)
#define KW 512                       // extended row: [hi(256)|lo(256)] in permuted k-order

#define XBUF (128 * 72 * 2)
#define EBUF (128 * 72 * 2)
#define NSTAGE 3
#define OFF_ES (NSTAGE * XBUF)
#define OFF_EN (NSTAGE * (XBUF + EBUF))
#define SMEM_DYN (OFF_EN + 512)

__device__ float g_enorm[K_CODES];
__device__ float g_xnorm[N_TOT];
__device__ unsigned long long g_best[N_TOT];
__device__ __half g_Xext[(size_t)N_TOT * KW];
__device__ __half g_Eext[(size_t)K_CODES * KW];

__device__ __forceinline__ uint32_t s2u(const void* p) {
    uint32_t a;
    asm("{ .reg .u64 t; cvta.to.shared.u64 t, %1; cvt.u32.u64 %0, t; }" : "=r"(a) : "l"(p));
    return a;
}
__device__ __forceinline__ void cp16(uint32_t d, const void* s) {
    asm volatile("cp.async.cg.shared.global [%0], [%1], 16;" :: "r"(d), "l"(s) : "memory");
}
__device__ __forceinline__ uint4 ldsm4(uint32_t a) {
    uint4 r;
    asm volatile("ldmatrix.sync.aligned.m8n8.x4.shared.b16 {%0,%1,%2,%3}, [%4];"
                 : "=r"(r.x), "=r"(r.y), "=r"(r.z), "=r"(r.w) : "r"(a));
    return r;
}
__device__ __forceinline__ void mma16816(float* d, uint4 a, uint32_t b0, uint32_t b1) {
    asm volatile("mma.sync.aligned.m16n8k16.row.col.f32.f16.f16.f32 "
                 "{%0,%1,%2,%3},{%4,%5,%6,%7},{%8,%9},{%0,%1,%2,%3};"
                 : "+f"(d[0]), "+f"(d[1]), "+f"(d[2]), "+f"(d[3])
                 : "r"(a.x), "r"(a.y), "r"(a.z), "r"(a.w), "r"(b0), "r"(b1));
}
__device__ __forceinline__ uint32_t mono(float f) {
    uint32_t u = __float_as_uint(f);
    return (u & 0x80000000u) ? ~u : (u | 0x80000000u);
}
__device__ __forceinline__ float unmono(uint32_t v) {
    uint32_t u = (v & 0x80000000u) ? (v & 0x7fffffffu) : ~v;
    return __uint_as_float(u);
}

// k-permutation: extended-row position p holds dim perm(p) = (p&7)*32 + (p>>3).
// Applied identically to X and E, so all dot products are unchanged.

// Merged prep: blocks [0,128) = E convert (permuted) + norms + loss init;
// blocks [128,128+2048) = X transpose/split (permuted) + ||x||^2 + g_best init.
__global__ void __launch_bounds__(256) prep_kernel(const float* __restrict__ X,
                                                   const float* __restrict__ E,
                                                   float* __restrict__ out) {
    if (blockIdx.x < 128) {
        if (blockIdx.x == 0 && threadIdx.x == 0) out[LOSS_OFF] = 0.0f;
        int k = blockIdx.x * 8 + (threadIdx.x >> 5);
        int lane = threadIdx.x & 31;
        const float* er = E + (size_t)k * D_DIM;
        __align__(16) __half hb[8], lb[8];
        float s = 0.f;
        #pragma unroll
        for (int q = 0; q < 8; q++) {
            float x = er[q * 32 + lane];      // dim perm(lane*8+q), coalesced in lane
            s = fmaf(x, x, s);
            __half h = __float2half_rn(x);
            hb[q] = h;
            lb[q] = __float2half_rn(x - __half2float(h));
        }
        __half* row = g_Eext + (size_t)k * KW;
        *(uint4*)(row + lane * 8) = *(uint4*)hb;
        *(uint4*)(row + 256 + lane * 8) = *(uint4*)lb;
        #pragma unroll
        for (int o = 16; o; o >>= 1) s += __shfl_down_sync(0xffffffffu, s, o);
        if (lane == 0) g_enorm[k] = 0.5f * s;
        return;
    }
    int bx = blockIdx.x - 128;
    int by = bx >> 6, bt = bx & 63;
    if (threadIdx.x < 32) g_best[bx * 32 + threadIdx.x] = ~0ull;
    __shared__ float tile[256][33];
    int lane = threadIdx.x & 31, w = threadIdx.x >> 5;
    const float* src = X + (size_t)by * D_DIM * T_DIM + bt * 32;
    #pragma unroll 8
    for (int r = 0; r < 32; r++) {
        int d = w + r * 8;
        tile[d][lane] = src[(size_t)d * T_DIM + lane];
    }
    __syncthreads();
    for (int i = 0; i < 4; i++) {
        int nl = w * 4 + i;
        int n = by * T_DIM + bt * 32 + nl;
        __align__(16) __half hb[8], lb[8];
        float s = 0.f;
        #pragma unroll
        for (int q = 0; q < 8; q++) {
            float x = tile[q * 32 + lane][nl];   // dim perm(lane*8+q); bank (lane+nl)%32: conflict-free
            s = fmaf(x, x, s);
            __half h = __float2half_rn(x);
            hb[q] = h;
            lb[q] = __float2half_rn(x - __half2float(h));
        }
        __half* row = g_Xext + (size_t)n * KW;
        *(uint4*)(row + lane * 8) = *(uint4*)hb;
        *(uint4*)(row + 256 + lane * 8) = *(uint4*)lb;
        #pragma unroll
        for (int o = 16; o; o >>= 1) s += __shfl_down_sync(0xffffffffu, s, o);
        if (lane == 0) g_xnorm[n] = s;
    }
}

// Argmin GEMM (R7/R11 schedule, verbatim): CTA = 128 x-rows x 128 codes,
// 12 chunks of K=64 (hi.hi, lo.hi, hi.lo), 3-stage cp.async (load after
// compute), 2 CTAs/SM, 8 warps of 64x32.
__global__ void __launch_bounds__(256, 2) vqmma_kernel() {
    extern __shared__ char sm[];
    const uint32_t sb = s2u(sm);
    float* en_s = (float*)(sm + OFF_EN);
    const int tid = threadIdx.x, wid = tid >> 5, lane = tid & 31;
    const int k0 = blockIdx.x * 128, n0 = blockIdx.y * 128;
    const int mw = wid & 1, nw = wid >> 1;   // 2 m-warps x 4 n-warps

    if (tid < 128) en_s[tid] = g_enorm[k0 + tid];

    float acc[64];
    #pragma unroll
    for (int i = 0; i < 64; i++) acc[i] = 0.f;

    auto load = [&](int g) {
        int t = g >> 2, c = (g & 3) * 64, buf = g % 3;
        int xoff = (t == 1 ? 256 : 0) + c;   // hi, lo, hi
        int eoff = (t == 2 ? 256 : 0) + c;   // hi, hi, lo
        const __half* xs = g_Xext + (size_t)n0 * KW + xoff;
        const __half* es = g_Eext + (size_t)k0 * KW + eoff;
        uint32_t xb = sb + buf * XBUF;
        uint32_t eb = sb + OFF_ES + buf * EBUF;
        #pragma unroll
        for (int q = 0; q < 4; q++) {
            int id = tid + q * 256, r = id >> 3, cc = id & 7;
            cp16(xb + (r * 72 + cc * 8) * 2, xs + (size_t)r * KW + cc * 8);
            cp16(eb + (r * 72 + cc * 8) * 2, es + (size_t)r * KW + cc * 8);
        }
        asm volatile("cp.async.commit_group;" ::: "memory");
    };

    load(0); load(1);

    const int l7 = lane & 7;
    const int arow = ((lane >> 3) & 1) * 8, akc = (lane >> 4) * 8;
    const int brow = (lane >> 4) * 8, bkc = ((lane >> 3) & 1) * 8;

    for (int g = 0; g < 12; g++) {
        if (g < 11) asm volatile("cp.async.wait_group 1;" ::: "memory");
        else        asm volatile("cp.async.wait_group 0;" ::: "memory");
        __syncthreads();
        int buf = g % 3;
        uint32_t xb = sb + buf * XBUF;
        uint32_t eb = sb + OFF_ES + buf * EBUF;
        #pragma unroll
        for (int ks = 0; ks < 4; ks++) {
            int kk = ks * 16;
            uint4 B[2];
            #pragma unroll
            for (int p = 0; p < 2; p++) {
                int nb = nw * 32 + p * 16;
                B[p] = ldsm4(eb + ((nb + l7 + brow) * 72 + kk + bkc) * 2);
            }
            #pragma unroll
            for (int mt = 0; mt < 4; mt++) {
                int m0 = mw * 64 + mt * 16;
                uint4 A = ldsm4(xb + ((m0 + l7 + arow) * 72 + kk + akc) * 2);
                #pragma unroll
                for (int p = 0; p < 2; p++) {
                    mma16816(&acc[(mt * 4 + p * 2 + 0) * 4], A, B[p].x, B[p].y);
                    mma16816(&acc[(mt * 4 + p * 2 + 1) * 4], A, B[p].z, B[p].w);
                }
            }
        }
        if (g + 2 < 12) load(g + 2);   // buf (g-1)%3, consumed last iter
    }

    // Argmin epilogue -> atomicMin packed (monotone score, code):
    // exact jnp.argmin first-index tie-break.
    #pragma unroll
    for (int mt = 0; mt < 4; mt++) {
        #pragma unroll
        for (int h = 0; h < 2; h++) {
            unsigned long long best = ~0ull;
            #pragma unroll
            for (int p = 0; p < 2; p++)
                #pragma unroll
                for (int b8 = 0; b8 < 2; b8++)
                    #pragma unroll
                    for (int c2 = 0; c2 < 2; c2++) {
                        int cl = nw * 32 + p * 16 + b8 * 8 + (lane & 3) * 2 + c2;
                        float sc = en_s[cl] - acc[(mt * 4 + p * 2 + b8) * 4 + h * 2 + c2];
                        unsigned long long pk =
                            ((unsigned long long)mono(sc) << 32) | (unsigned)(k0 + cl);
                        if (pk < best) best = pk;
                    }
            unsigned long long o1 = __shfl_xor_sync(0xffffffffu, best, 1);
            if (o1 < best) best = o1;
            unsigned long long o2 = __shfl_xor_sync(0xffffffffu, best, 2);
            if (o2 < best) best = o2;
            if ((lane & 3) == 0) {
                int row = n0 + mw * 64 + mt * 16 + (lane >> 2) + h * 8;
                atomicMin(&g_best[row], best);
            }
        }
    }
}

// Gather + transpose-write + loss. No X reads: loss comes from the packed
// best score: ||x - e_j||^2 = ||x||^2 + 2*(0.5||e_j||^2 - x.e_j).
__global__ void __launch_bounds__(256) gather_loss_kernel(const float* __restrict__ E,
                                                          float* __restrict__ out) {
    __shared__ float ws[8];
    int t = blockIdx.x * 64 + (threadIdx.x & 63);
    int dseg = threadIdx.x >> 6;
    int b = blockIdx.y;
    int n = b * T_DIM + t;
    unsigned long long pk = g_best[n];
    int j = (int)(unsigned)(pk & 0xffffffffull);
    float s = 0.f;
    if (dseg == 0) {
        out[IDX_OFF + n] = (float)j;
        float score = unmono((uint32_t)(pk >> 32));
        s = g_xnorm[n] + 2.0f * score;        // ||x_n - e_j||^2
    }
    const float* er = E + (size_t)j * D_DIM + dseg * 64;
    float* orow = out + (size_t)b * D_DIM * T_DIM + (size_t)dseg * 64 * T_DIM + t;
    #pragma unroll 4
    for (int d = 0; d < 64; d += 4) {
        float4 e4 = *(const float4*)(er + d);
        orow[(size_t)(d + 0) * T_DIM] = e4.x;
        orow[(size_t)(d + 1) * T_DIM] = e4.y;
        orow[(size_t)(d + 2) * T_DIM] = e4.z;
        orow[(size_t)(d + 3) * T_DIM] = e4.w;
    }
    #pragma unroll
    for (int o = 16; o; o >>= 1) s += __shfl_down_sync(0xffffffffu, s, o);
    if ((threadIdx.x & 31) == 0) ws[threadIdx.x >> 5] = s;
    __syncthreads();
    if (threadIdx.x < 8) {
        float v = ws[threadIdx.x];
        #pragma unroll
        for (int o = 4; o; o >>= 1) v += __shfl_down_sync(0xffu, v, o);
        if (threadIdx.x == 0) atomicAdd(out + LOSS_OFF, v * (0.5f / (float)Q_ELEMS));
    }
}

extern "C" void kernel_launch(void* const* d_in, const int* in_sizes, int n_in,
                              void* d_out, int out_size) {
    const float* X = (const float*)d_in[0];
    const float* E = (const float*)d_in[1];
    float* out = (float*)d_out;
    prep_kernel<<<128 + 2048, 256>>>(X, E, out);
    cudaFuncSetAttribute(vqmma_kernel, cudaFuncAttributeMaxDynamicSharedMemorySize, SMEM_DYN);
    // ktile-major grid: 8 CTAs sharing an x-tile are bid-adjacent -> L2 reuse of X.
    vqmma_kernel<<<dim3(K_CODES / 128, N_TOT / 128), 256, SMEM_DYN>>>();
    gather_loss_kernel<<<dim3(T_DIM / 64, B_DIM), 256>>>(E, out);
}